// round 2
// baseline (speedup 1.0000x reference)
#include <cuda_runtime.h>
#include <cstdint>

// PackedViterbi (logsumexp semiring) forward.
// theta: [T=256, B=32, S=128, S=128] fp32.  out: [B=32] fp32.
//
// 128 CTAs (4 per batch), 256 threads each. Each CTA owns 32 output rows of
// one batch. Per timestep: logsumexp over j of (theta[t,b,i,j] + V[b,j]),
// with V exchanged across the 4 sibling CTAs through L2 (fence + flag).
// theta is prefetched 4 steps ahead with cp.async into a 5-slot shared ring.

#define NT   256   // timesteps
#define NB   32    // batch
#define NS   128   // states
#define SUBS 4     // CTAs per batch
#define RPC  32    // rows per CTA
#define NTHR 256
#define TILE_BYTES (RPC * NS * 4)   // 16384
#define PIPE 5
#define DIST 4

__device__ float    g_V[2][NB][NS];       // V in base-2 log domain, parity-buffered
__device__ unsigned g_cnt[NT][NB];        // per-step completion counters (memset each launch)

static __device__ __forceinline__ float ex2f_(float x) {
    float y; asm("ex2.approx.ftz.f32 %0, %1;" : "=f"(y) : "f"(x)); return y;
}
static __device__ __forceinline__ float lg2f_(float x) {
    float y; asm("lg2.approx.ftz.f32 %0, %1;" : "=f"(y) : "f"(x)); return y;
}
static __device__ __forceinline__ void cp16(unsigned d, const void* s) {
    asm volatile("cp.async.cg.shared.global [%0], [%1], 16;" :: "r"(d), "l"(s));
}
static __device__ __forceinline__ unsigned ld_acq(const unsigned* p) {
    unsigned v;
    asm volatile("ld.acquire.gpu.global.u32 %0, [%1];" : "=r"(v) : "l"(p));
    return v;
}

extern "C" __global__ void __launch_bounds__(NTHR, 1)
viterbi_fwd(const float* __restrict__ theta, float* __restrict__ out)
{
    extern __shared__ float4 smem[];   // PIPE * 1024 float4
    const int cta  = blockIdx.x;
    const int bb   = cta >> 2;         // batch
    const int sub  = cta & 3;          // which quarter of the rows
    const int tid  = threadIdx.x;
    const int lane = tid & 31;
    const int warp = tid >> 5;
    const int rg   = lane >> 3;        // row within warp's 4-row group
    const int sl   = lane & 7;         // sub-lane within 8-lane reduction group
    const int rowL = (warp << 2) + rg; // local row 0..31
    const int irow = sub * RPC + rowL; // global state index i

    const size_t tstride = (size_t)NB * NS * NS;  // floats per timestep
    const float* base = theta + ((size_t)bb * NS + (size_t)sub * RPC) * NS;
    unsigned sbase = (unsigned)__cvta_generic_to_shared(smem);

    // ---- prologue: prefetch stages 0..DIST-1 ----
#pragma unroll
    for (int s = 0; s < DIST; ++s) {
        const char* src = (const char*)(base + (size_t)s * tstride);
        unsigned dst = sbase + s * TILE_BYTES;
#pragma unroll
        for (int k = 0; k < 4; ++k) {
            int off = (tid + k * NTHR) << 4;
            cp16(dst + off, src + off);
        }
        asm volatile("cp.async.commit_group;");
    }

    const float LOG2E = 1.4426950408889634f;
    const unsigned FULL = 0xffffffffu;

    for (int t = 0; t < NT; ++t) {
        // stage t ready (invariant: exactly DIST groups pending at this point)
        asm volatile("cp.async.wait_group %0;" :: "n"(DIST - 1));

        // issue prefetch for t+DIST (empty commit in tail keeps group count uniform)
        if (t + DIST < NT) {
            const char* src = (const char*)(base + (size_t)(t + DIST) * tstride);
            unsigned dst = sbase + ((t + DIST) % PIPE) * TILE_BYTES;
#pragma unroll
            for (int k = 0; k < 4; ++k) {
                int off = (tid + k * NTHR) << 4;
                cp16(dst + off, src + off);
            }
        }
        asm volatile("cp.async.commit_group;");

        // wait for V_t from all 4 sibling CTAs
        if (t > 0 && tid == 0) {
            const unsigned* p = &g_cnt[t - 1][bb];
            while (ld_acq(p) < (unsigned)SUBS) { }
        }
        __syncthreads();

        // load V_t (base-2 domain); j = sl*4 + 32c  -> float4 index sl + 8c
        float4 v0, v1, v2, v3;
        if (t == 0) {
            v0 = make_float4(0.f, 0.f, 0.f, 0.f); v1 = v0; v2 = v0; v3 = v0;
        } else {
            const float4* V = (const float4*)(g_V[t & 1][bb]);
            v0 = __ldcv(V + sl);
            v1 = __ldcv(V + sl + 8);
            v2 = __ldcv(V + sl + 16);
            v3 = __ldcv(V + sl + 24);
        }

        const float4* tile = smem + (size_t)(t % PIPE) * (TILE_BYTES / 16);
        const float4* rp   = tile + rowL * (NS / 4) + sl;
        float4 a0 = rp[0], a1 = rp[8], a2 = rp[16], a3 = rp[24];

        // x = theta*log2(e) + V2
        float x0  = fmaf(a0.x, LOG2E, v0.x);
        float x1  = fmaf(a0.y, LOG2E, v0.y);
        float x2  = fmaf(a0.z, LOG2E, v0.z);
        float x3  = fmaf(a0.w, LOG2E, v0.w);
        float x4  = fmaf(a1.x, LOG2E, v1.x);
        float x5  = fmaf(a1.y, LOG2E, v1.y);
        float x6  = fmaf(a1.z, LOG2E, v1.z);
        float x7  = fmaf(a1.w, LOG2E, v1.w);
        float x8  = fmaf(a2.x, LOG2E, v2.x);
        float x9  = fmaf(a2.y, LOG2E, v2.y);
        float x10 = fmaf(a2.z, LOG2E, v2.z);
        float x11 = fmaf(a2.w, LOG2E, v2.w);
        float x12 = fmaf(a3.x, LOG2E, v3.x);
        float x13 = fmaf(a3.y, LOG2E, v3.y);
        float x14 = fmaf(a3.z, LOG2E, v3.z);
        float x15 = fmaf(a3.w, LOG2E, v3.w);

        float m = fmaxf(fmaxf(fmaxf(x0, x1), fmaxf(x2, x3)),
                        fmaxf(fmaxf(x4, x5), fmaxf(x6, x7)));
        m = fmaxf(m, fmaxf(fmaxf(fmaxf(x8, x9), fmaxf(x10, x11)),
                           fmaxf(fmaxf(x12, x13), fmaxf(x14, x15))));
        m = fmaxf(m, __shfl_xor_sync(FULL, m, 1));
        m = fmaxf(m, __shfl_xor_sync(FULL, m, 2));
        m = fmaxf(m, __shfl_xor_sync(FULL, m, 4));

        float s = ex2f_(x0 - m)  + ex2f_(x1 - m)  + ex2f_(x2 - m)  + ex2f_(x3 - m)
                + ex2f_(x4 - m)  + ex2f_(x5 - m)  + ex2f_(x6 - m)  + ex2f_(x7 - m)
                + ex2f_(x8 - m)  + ex2f_(x9 - m)  + ex2f_(x10 - m) + ex2f_(x11 - m)
                + ex2f_(x12 - m) + ex2f_(x13 - m) + ex2f_(x14 - m) + ex2f_(x15 - m);
        s += __shfl_xor_sync(FULL, s, 1);
        s += __shfl_xor_sync(FULL, s, 2);
        s += __shfl_xor_sync(FULL, s, 4);

        float vnew = m + lg2f_(s);
        if (sl == 0) g_V[(t + 1) & 1][bb][irow] = vnew;

        __threadfence();          // publish V stores gpu-wide
        __syncthreads();
        if (tid == 0) atomicAdd(&g_cnt[t][bb], 1u);
    }

    // ---- epilogue: terminal logsumexp over states (sub==0 CTA only) ----
    if (sub == 0) {
        if (tid == 0) {
            const unsigned* p = &g_cnt[NT - 1][bb];
            while (ld_acq(p) < (unsigned)SUBS) { }
        }
        __syncthreads();
        if (warp == 0) {
            const float* Vf = g_V[NT & 1][bb];   // NT even -> buffer 0
            float a  = __ldcv(Vf + lane);
            float c1 = __ldcv(Vf + lane + 32);
            float c2 = __ldcv(Vf + lane + 64);
            float c3 = __ldcv(Vf + lane + 96);
            float m = fmaxf(fmaxf(a, c1), fmaxf(c2, c3));
#pragma unroll
            for (int o = 16; o; o >>= 1) m = fmaxf(m, __shfl_xor_sync(FULL, m, o));
            float s = ex2f_(a - m) + ex2f_(c1 - m) + ex2f_(c2 - m) + ex2f_(c3 - m);
#pragma unroll
            for (int o = 16; o; o >>= 1) s += __shfl_xor_sync(FULL, s, o);
            if (lane == 0)
                out[bb] = 0.6931471805599453f * (m + lg2f_(s));  // back to natural log
        }
    }
}

extern "C" void kernel_launch(void* const* d_in, const int* in_sizes, int n_in,
                              void* d_out, int out_size)
{
    (void)in_sizes; (void)n_in; (void)out_size;
    const float* theta = (const float*)d_in[0];
    float* out = (float*)d_out;

    void* cnt_ptr = nullptr;
    cudaGetSymbolAddress(&cnt_ptr, g_cnt);
    cudaMemsetAsync(cnt_ptr, 0, sizeof(unsigned) * NT * NB);

    cudaFuncSetAttribute(viterbi_fwd,
                         cudaFuncAttributeMaxDynamicSharedMemorySize,
                         PIPE * TILE_BYTES);
    viterbi_fwd<<<NB * SUBS, NTHR, PIPE * TILE_BYTES>>>(theta, out);
}

// round 3
// speedup vs baseline: 1.3470x; 1.3470x over previous
#include <cuda_runtime.h>
#include <cstdint>

// PackedViterbi (logsumexp semiring) forward.
// theta: [T=256, B=32, S=128, S=128] fp32.  out: [B=32] fp32.
//
// 32 clusters of 4 CTAs (one cluster per batch), 256 threads per CTA.
// Each CTA owns 32 output rows. Per timestep the 128 new V values are
// exchanged across the cluster with st.async -> remote SMEM + mbarrier.
// exp(theta) is precomputed one step ahead into registers (off the chain).
// Running-offset renormalization removes the per-row max entirely.

#define NT   256
#define NB   32
#define NS   128
#define RPC  32
#define NTHR 256
#define TILE_BYTES (RPC * NS * 4)    // 16384
#define PIPE 6
#define DIST 4
#define LOG2E 1.4426950408889634f
#define FULLM 0xffffffffu

static __device__ __forceinline__ float ex2f_(float x) {
    float y; asm("ex2.approx.ftz.f32 %0, %1;" : "=f"(y) : "f"(x)); return y;
}
static __device__ __forceinline__ float lg2f_(float x) {
    float y; asm("lg2.approx.ftz.f32 %0, %1;" : "=f"(y) : "f"(x)); return y;
}
static __device__ __forceinline__ void cp16(unsigned d, const void* s) {
    asm volatile("cp.async.cg.shared.global [%0], [%1], 16;" :: "r"(d), "l"(s));
}
static __device__ __forceinline__ void prime(unsigned bar) {
    asm volatile("mbarrier.arrive.expect_tx.release.cluster.shared::cta.b64 _, [%0], 512;"
                 :: "r"(bar) : "memory");
}
static __device__ __forceinline__ void waitc(unsigned bar, unsigned ph) {
    asm volatile(
        "{\n\t"
        ".reg .pred P;\n"
        "WL%=:\n\t"
        "mbarrier.try_wait.parity.acquire.cluster.shared::cta.b64 P, [%0], %1, 0x989680;\n\t"
        "@P bra WD%=;\n\t"
        "bra WL%=;\n"
        "WD%=:\n\t"
        "}" :: "r"(bar), "r"(ph) : "memory");
}
static __device__ __forceinline__ void st_async32(unsigned daddr, float v, unsigned dbar) {
    asm volatile("st.async.shared::cluster.mbarrier::complete_tx::bytes.b32 [%0], %1, [%2];"
                 :: "r"(daddr), "r"(__float_as_uint(v)), "r"(dbar) : "memory");
}

extern "C" __global__ void __launch_bounds__(NTHR, 1) __cluster_dims__(4, 1, 1)
viterbi_fwd(const float* __restrict__ theta, float* __restrict__ out)
{
    extern __shared__ float4 ring[];            // PIPE * 1024 float4
    __shared__ float sV[2][NS];                 // received V' (base-2 log domain)
    __shared__ float sEV[NS];                   // exp2(V')
    __shared__ __align__(8) unsigned long long sbar[2];

    const int tid  = threadIdx.x;
    const int lane = tid & 31;
    const int warp = tid >> 5;
    const int sl   = lane & 7;          // 8 lanes per row
    const int rg   = lane >> 3;
    const int rowL = (warp << 2) + rg;  // local row 0..31
    const int bid  = blockIdx.x;
    const int bb   = bid >> 2;          // batch
    const int sub  = bid & 3;           // cluster rank
    const int irow = sub * RPC + rowL;

    unsigned rbase = (unsigned)__cvta_generic_to_shared(ring);
    unsigned vbase = (unsigned)__cvta_generic_to_shared(&sV[0][0]);
    unsigned bbase = (unsigned)__cvta_generic_to_shared(&sbar[0]);

    if (tid == 0) {
        asm volatile("mbarrier.init.shared.b64 [%0], 1;" :: "r"(bbase)     : "memory");
        asm volatile("mbarrier.init.shared.b64 [%0], 1;" :: "r"(bbase + 8) : "memory");
        asm volatile("fence.mbarrier_init.release.cluster;" ::: "memory");
        prime(bbase);        // bar0 phase 0 (receives V_2)
        prime(bbase + 8);    // bar1 phase 0 (receives V_1)
    }
    __syncthreads();
    asm volatile("barrier.cluster.arrive.aligned;" ::: "memory");
    asm volatile("barrier.cluster.wait.aligned;"   ::: "memory");

    // per-rank remote SMEM base addresses (offsets within a CTA are preserved)
    unsigned rV[4], rB[4];
#pragma unroll
    for (int r = 0; r < 4; ++r) {
        asm("mapa.shared::cluster.u32 %0, %1, %2;" : "=r"(rV[r]) : "r"(vbase), "r"(r));
        asm("mapa.shared::cluster.u32 %0, %1, %2;" : "=r"(rB[r]) : "r"(bbase), "r"(r));
    }

    const size_t tstride = (size_t)NB * NS * NS;
    const float* base = theta + ((size_t)bb * NS + (size_t)sub * RPC) * NS;

    // ---- prologue: prefetch stages 0..DIST-1 ----
#pragma unroll
    for (int s = 0; s < DIST; ++s) {
        const char* src = (const char*)(base + (size_t)s * tstride);
        unsigned dst = rbase + s * TILE_BYTES;
#pragma unroll
        for (int k2 = 0; k2 < 4; ++k2) {
            int o = (tid + k2 * NTHR) << 4;
            cp16(dst + o, src + o);
        }
        asm volatile("cp.async.commit_group;");
    }

    float Ea[16], Eb[16];
    unsigned ph0 = 0, ph1 = 0;
    float off = 0.f;

    // stage 0 -> Ea
    asm volatile("cp.async.wait_group 3;");
    {
        const float4* tp = ring + rowL * (NS / 4) + sl;
        float4 a0 = tp[0], a1 = tp[8], a2 = tp[16], a3 = tp[24];
        Ea[0]  = ex2f_(a0.x * LOG2E); Ea[1]  = ex2f_(a0.y * LOG2E);
        Ea[2]  = ex2f_(a0.z * LOG2E); Ea[3]  = ex2f_(a0.w * LOG2E);
        Ea[4]  = ex2f_(a1.x * LOG2E); Ea[5]  = ex2f_(a1.y * LOG2E);
        Ea[6]  = ex2f_(a1.z * LOG2E); Ea[7]  = ex2f_(a1.w * LOG2E);
        Ea[8]  = ex2f_(a2.x * LOG2E); Ea[9]  = ex2f_(a2.y * LOG2E);
        Ea[10] = ex2f_(a2.z * LOG2E); Ea[11] = ex2f_(a2.w * LOG2E);
        Ea[12] = ex2f_(a3.x * LOG2E); Ea[13] = ex2f_(a3.y * LOG2E);
        Ea[14] = ex2f_(a3.z * LOG2E); Ea[15] = ex2f_(a3.w * LOG2E);
    }

    auto step = [&](int t, int par, float (&Ecur)[16], float (&Enext)[16]) {
        // 1. stage t+1 is ready; issue prefetch for t+DIST
        asm volatile("cp.async.wait_group 2;");
        if (t + DIST < NT) {
            const char* src = (const char*)(base + (size_t)(t + DIST) * tstride);
            unsigned dst = rbase + ((t + DIST) % PIPE) * TILE_BYTES;
#pragma unroll
            for (int k2 = 0; k2 < 4; ++k2) {
                int o = (tid + k2 * NTHR) << 4;
                cp16(dst + o, src + o);
            }
        }
        asm volatile("cp.async.commit_group;");

        // 2. transform stage t+1 -> Enext (off the V critical path)
        if (t + 1 < NT) {
            const float4* tp = ring + ((t + 1) % PIPE) * (TILE_BYTES / 16)
                             + rowL * (NS / 4) + sl;
            float4 a0 = tp[0], a1 = tp[8], a2 = tp[16], a3 = tp[24];
            Enext[0]  = ex2f_(a0.x * LOG2E); Enext[1]  = ex2f_(a0.y * LOG2E);
            Enext[2]  = ex2f_(a0.z * LOG2E); Enext[3]  = ex2f_(a0.w * LOG2E);
            Enext[4]  = ex2f_(a1.x * LOG2E); Enext[5]  = ex2f_(a1.y * LOG2E);
            Enext[6]  = ex2f_(a1.z * LOG2E); Enext[7]  = ex2f_(a1.w * LOG2E);
            Enext[8]  = ex2f_(a2.x * LOG2E); Enext[9]  = ex2f_(a2.y * LOG2E);
            Enext[10] = ex2f_(a2.z * LOG2E); Enext[11] = ex2f_(a2.w * LOG2E);
            Enext[12] = ex2f_(a3.x * LOG2E); Enext[13] = ex2f_(a3.y * LOG2E);
            Enext[14] = ex2f_(a3.z * LOG2E); Enext[15] = ex2f_(a3.w * LOG2E);
        }

        // 3. wait for V_t, build exp2(V) table
        float r;
        if (t > 0) {
            unsigned bar = bbase + 8 * par;
            waitc(bar, par ? ph1 : ph0);
            if (par) ph1 ^= 1; else ph0 ^= 1;
            if (tid == 0) prime(bar);          // re-arm for step t+2 (before any send)
            if (tid < NS) sEV[tid] = ex2f_(sV[par][tid]);
            r = sV[par][0];
        } else {
            if (tid < NS) sEV[tid] = 1.f;
            r = 0.f;
        }
        __syncthreads();
        off += r;

        // 4. dot product + 8-lane reduce + send
        const float4* evp = (const float4*)sEV;
        float4 e0 = evp[sl], e1 = evp[sl + 8], e2 = evp[sl + 16], e3 = evp[sl + 24];
        float s0 = Ecur[0] * e0.x;
        s0 = fmaf(Ecur[1],  e0.y, s0); s0 = fmaf(Ecur[2],  e0.z, s0); s0 = fmaf(Ecur[3],  e0.w, s0);
        float s1 = Ecur[4] * e1.x;
        s1 = fmaf(Ecur[5],  e1.y, s1); s1 = fmaf(Ecur[6],  e1.z, s1); s1 = fmaf(Ecur[7],  e1.w, s1);
        float s2 = Ecur[8] * e2.x;
        s2 = fmaf(Ecur[9],  e2.y, s2); s2 = fmaf(Ecur[10], e2.z, s2); s2 = fmaf(Ecur[11], e2.w, s2);
        float s3 = Ecur[12] * e3.x;
        s3 = fmaf(Ecur[13], e3.y, s3); s3 = fmaf(Ecur[14], e3.z, s3); s3 = fmaf(Ecur[15], e3.w, s3);
        float s = (s0 + s1) + (s2 + s3);
        s += __shfl_xor_sync(FULLM, s, 1);
        s += __shfl_xor_sync(FULLM, s, 2);
        s += __shfl_xor_sync(FULLM, s, 4);

        float vst = lg2f_(s) - r;              // renormalized V'_{t+1}[irow]
        if (sl == 0) {
            int k1 = (t + 1) & 1;
            unsigned voff = (unsigned)(k1 * (NS * 4) + irow * 4);
            unsigned boff = (unsigned)(8 * k1);
#pragma unroll
            for (int rr = 0; rr < 4; ++rr)
                st_async32(rV[rr] + voff, vst, rB[rr] + boff);
        }
    };

    for (int t = 0; t < NT; t += 2) {
        step(t,     0, Ea, Eb);
        step(t + 1, 1, Eb, Ea);
    }

    // ---- epilogue: V_NT arrives on bar0/buf0; rank 0 reduces ----
    if (sub == 0) {
        waitc(bbase, ph0);
        if (warp == 0) {
            float a = sV[0][lane];
            float b = sV[0][lane + 32];
            float c = sV[0][lane + 64];
            float d = sV[0][lane + 96];
            float s = ex2f_(a) + ex2f_(b) + ex2f_(c) + ex2f_(d);
#pragma unroll
            for (int o = 16; o; o >>= 1) s += __shfl_xor_sync(FULLM, s, o);
            if (lane == 0)
                out[bb] = 0.6931471805599453f * (off + lg2f_(s));
        }
    }
    asm volatile("barrier.cluster.arrive.aligned;" ::: "memory");
    asm volatile("barrier.cluster.wait.aligned;"   ::: "memory");
}

extern "C" void kernel_launch(void* const* d_in, const int* in_sizes, int n_in,
                              void* d_out, int out_size)
{
    (void)in_sizes; (void)n_in; (void)out_size;
    const float* theta = (const float*)d_in[0];
    float* out = (float*)d_out;

    cudaFuncSetAttribute(viterbi_fwd,
                         cudaFuncAttributeMaxDynamicSharedMemorySize,
                         PIPE * TILE_BYTES);
    viterbi_fwd<<<NB * 4, NTHR, PIPE * TILE_BYTES>>>(theta, out);
}

// round 4
// speedup vs baseline: 4.0695x; 3.0211x over previous
#include <cuda_runtime.h>
#include <cstdint>

// PackedViterbi (logsumexp semiring) forward.
// theta: [T=256, B=32, S=128, S=128] fp32.  out: [B=32] fp32.
//
// 32 clusters of 4 CTAs (one per batch), 256 threads per CTA, 32 rows each.
// Per-step V exchange: tagged 64-bit plain DSMEM stores + smem polling
// (no mbarrier, no cluster-scope acquire). exp(theta) precomputed one step
// ahead; running-offset renormalization removes the per-row max.

#define NT   256
#define NB   32
#define NS   128
#define RPC  32
#define NTHR 256
#define TILE_BYTES (RPC * NS * 4)    // 16384
#define PIPE 6
#define DIST 4
#define LOG2E 1.4426950408889634f
#define FULLM 0xffffffffu

static __device__ __forceinline__ float ex2f_(float x) {
    float y; asm("ex2.approx.ftz.f32 %0, %1;" : "=f"(y) : "f"(x)); return y;
}
static __device__ __forceinline__ float lg2f_(float x) {
    float y; asm("lg2.approx.ftz.f32 %0, %1;" : "=f"(y) : "f"(x)); return y;
}
static __device__ __forceinline__ void cp16(unsigned d, const void* s) {
    asm volatile("cp.async.cg.shared.global [%0], [%1], 16;" :: "r"(d), "l"(s));
}
static __device__ __forceinline__ void st_dsmem64(unsigned daddr, unsigned long long v) {
    asm volatile("st.relaxed.cluster.shared::cluster.b64 [%0], %1;"
                 :: "r"(daddr), "l"(v) : "memory");
}
static __device__ __forceinline__ unsigned long long ld_vol64(unsigned addr) {
    unsigned long long v;
    asm volatile("ld.volatile.shared.b64 %0, [%1];" : "=l"(v) : "r"(addr));
    return v;
}

extern "C" __global__ void __launch_bounds__(NTHR, 1) __cluster_dims__(4, 1, 1)
viterbi_fwd(const float* __restrict__ theta, float* __restrict__ out)
{
    extern __shared__ float4 ring[];                     // PIPE * 1024 float4
    __shared__ __align__(8) unsigned long long sV[2][NS]; // tagged V' slots
    __shared__ float sEV[2][NS];                          // exp2(V') tables

    const int tid  = threadIdx.x;
    const int lane = tid & 31;
    const int warp = tid >> 5;
    const int sl   = lane & 7;
    const int rg   = lane >> 3;
    const int rowL = (warp << 2) + rg;   // local row 0..31
    const int bid  = blockIdx.x;
    const int bb   = bid >> 2;
    const int sub  = bid & 3;            // cluster rank
    const int irow = sub * RPC + rowL;

    unsigned rbase = (unsigned)__cvta_generic_to_shared(ring);
    unsigned vbase = (unsigned)__cvta_generic_to_shared(&sV[0][0]);

    // zero tags before any peer can write
    ((unsigned long long*)sV)[tid] = 0ull;
    __syncthreads();
    asm volatile("barrier.cluster.arrive.aligned;" ::: "memory");
    asm volatile("barrier.cluster.wait.aligned;"   ::: "memory");

    unsigned rV[4];
#pragma unroll
    for (int r = 0; r < 4; ++r)
        asm("mapa.shared::cluster.u32 %0, %1, %2;" : "=r"(rV[r]) : "r"(vbase), "r"(r));

    const size_t tstride = (size_t)NB * NS * NS;
    const float* base = theta + ((size_t)bb * NS + (size_t)sub * RPC) * NS;

    // ---- prologue: prefetch stages 0..DIST-1 ----
#pragma unroll
    for (int s = 0; s < DIST; ++s) {
        const char* src = (const char*)(base + (size_t)s * tstride);
        unsigned dst = rbase + s * TILE_BYTES;
#pragma unroll
        for (int k2 = 0; k2 < 4; ++k2) {
            int o = (tid + k2 * NTHR) << 4;
            cp16(dst + o, src + o);
        }
        asm volatile("cp.async.commit_group;");
    }

    float Ea[16], Eb[16];
    float off = 0.f;

    // stage 0 -> Ea
    asm volatile("cp.async.wait_group 3;");
    {
        const float4* tp = ring + rowL * (NS / 4) + sl;
        float4 a0 = tp[0], a1 = tp[8], a2 = tp[16], a3 = tp[24];
        Ea[0]  = ex2f_(a0.x * LOG2E); Ea[1]  = ex2f_(a0.y * LOG2E);
        Ea[2]  = ex2f_(a0.z * LOG2E); Ea[3]  = ex2f_(a0.w * LOG2E);
        Ea[4]  = ex2f_(a1.x * LOG2E); Ea[5]  = ex2f_(a1.y * LOG2E);
        Ea[6]  = ex2f_(a1.z * LOG2E); Ea[7]  = ex2f_(a1.w * LOG2E);
        Ea[8]  = ex2f_(a2.x * LOG2E); Ea[9]  = ex2f_(a2.y * LOG2E);
        Ea[10] = ex2f_(a2.z * LOG2E); Ea[11] = ex2f_(a2.w * LOG2E);
        Ea[12] = ex2f_(a3.x * LOG2E); Ea[13] = ex2f_(a3.y * LOG2E);
        Ea[14] = ex2f_(a3.z * LOG2E); Ea[15] = ex2f_(a3.w * LOG2E);
    }

    auto step = [&](int t, int par, float (&Ecur)[16], float (&Enext)[16]) {
        // 1. stage t+1 ready; prefetch t+DIST
        asm volatile("cp.async.wait_group 2;");
        if (t + DIST < NT) {
            const char* src = (const char*)(base + (size_t)(t + DIST) * tstride);
            unsigned dst = rbase + ((t + DIST) % PIPE) * TILE_BYTES;
#pragma unroll
            for (int k2 = 0; k2 < 4; ++k2) {
                int o = (tid + k2 * NTHR) << 4;
                cp16(dst + o, src + o);
            }
        }
        asm volatile("cp.async.commit_group;");

        // 2. transform stage t+1 -> Enext (shadow work, off the V chain)
        if (t + 1 < NT) {
            const float4* tp = ring + ((t + 1) % PIPE) * (TILE_BYTES / 16)
                             + rowL * (NS / 4) + sl;
            float4 a0 = tp[0], a1 = tp[8], a2 = tp[16], a3 = tp[24];
            Enext[0]  = ex2f_(a0.x * LOG2E); Enext[1]  = ex2f_(a0.y * LOG2E);
            Enext[2]  = ex2f_(a0.z * LOG2E); Enext[3]  = ex2f_(a0.w * LOG2E);
            Enext[4]  = ex2f_(a1.x * LOG2E); Enext[5]  = ex2f_(a1.y * LOG2E);
            Enext[6]  = ex2f_(a1.z * LOG2E); Enext[7]  = ex2f_(a1.w * LOG2E);
            Enext[8]  = ex2f_(a2.x * LOG2E); Enext[9]  = ex2f_(a2.y * LOG2E);
            Enext[10] = ex2f_(a2.z * LOG2E); Enext[11] = ex2f_(a2.w * LOG2E);
            Enext[12] = ex2f_(a3.x * LOG2E); Enext[13] = ex2f_(a3.y * LOG2E);
            Enext[14] = ex2f_(a3.z * LOG2E); Enext[15] = ex2f_(a3.w * LOG2E);
        }

        // 3. poll V_t slot, build exp2 table entry
        float r = 0.f;
        if (tid < NS) {
            if (t == 0) {
                sEV[0][tid] = 1.f;
            } else {
                unsigned a = vbase + (unsigned)((par * NS + tid) * 8);
                unsigned long long v;
                do { v = ld_vol64(a); } while ((unsigned)(v >> 32) != (unsigned)t);
                sEV[par][tid] = ex2f_(__uint_as_float((unsigned)v));
            }
        }
        __syncthreads();
        if (t > 0) r = __uint_as_float((unsigned)ld_vol64(vbase + (unsigned)(par * NS * 8)));
        off += r;

        // 4. dot product + 8-lane reduce + tagged send
        const float4* evp = (const float4*)sEV[par];
        float4 e0 = evp[sl], e1 = evp[sl + 8], e2 = evp[sl + 16], e3 = evp[sl + 24];
        float s0 = Ecur[0] * e0.x;
        s0 = fmaf(Ecur[1],  e0.y, s0); s0 = fmaf(Ecur[2],  e0.z, s0); s0 = fmaf(Ecur[3],  e0.w, s0);
        float s1 = Ecur[4] * e1.x;
        s1 = fmaf(Ecur[5],  e1.y, s1); s1 = fmaf(Ecur[6],  e1.z, s1); s1 = fmaf(Ecur[7],  e1.w, s1);
        float s2 = Ecur[8] * e2.x;
        s2 = fmaf(Ecur[9],  e2.y, s2); s2 = fmaf(Ecur[10], e2.z, s2); s2 = fmaf(Ecur[11], e2.w, s2);
        float s3 = Ecur[12] * e3.x;
        s3 = fmaf(Ecur[13], e3.y, s3); s3 = fmaf(Ecur[14], e3.z, s3); s3 = fmaf(Ecur[15], e3.w, s3);
        float s = (s0 + s1) + (s2 + s3);
        s += __shfl_xor_sync(FULLM, s, 1);
        s += __shfl_xor_sync(FULLM, s, 2);
        s += __shfl_xor_sync(FULLM, s, 4);

        if (sl == 0) {
            float vst = lg2f_(s) - r;
            unsigned long long pkt = ((unsigned long long)(unsigned)(t + 1) << 32)
                                   | (unsigned long long)__float_as_uint(vst);
            int k1 = (t + 1) & 1;
            unsigned voff = (unsigned)((k1 * NS + irow) * 8);
#pragma unroll
            for (int rr = 0; rr < 4; ++rr)
                st_dsmem64(rV[rr] + voff, pkt);
        }
    };

    for (int t = 0; t < NT; t += 2) {
        step(t,     0, Ea, Eb);
        step(t + 1, 1, Eb, Ea);
    }

    // ---- epilogue: V_NT (tag NT) lands in buffer 0; rank 0 reduces ----
    if (sub == 0) {
        if (tid < NS) {
            unsigned a = vbase + (unsigned)(tid * 8);
            unsigned long long v;
            do { v = ld_vol64(a); } while ((unsigned)(v >> 32) != (unsigned)NT);
        }
        __syncthreads();
        if (warp == 0) {
            float a = __uint_as_float((unsigned)ld_vol64(vbase + lane * 8));
            float b = __uint_as_float((unsigned)ld_vol64(vbase + (lane + 32) * 8));
            float c = __uint_as_float((unsigned)ld_vol64(vbase + (lane + 64) * 8));
            float d = __uint_as_float((unsigned)ld_vol64(vbase + (lane + 96) * 8));
            float s = ex2f_(a) + ex2f_(b) + ex2f_(c) + ex2f_(d);
#pragma unroll
            for (int o = 16; o; o >>= 1) s += __shfl_xor_sync(FULLM, s, o);
            if (lane == 0)
                out[bb] = 0.6931471805599453f * (off + lg2f_(s));
        }
    }
    asm volatile("barrier.cluster.arrive.aligned;" ::: "memory");
    asm volatile("barrier.cluster.wait.aligned;"   ::: "memory");
}

extern "C" void kernel_launch(void* const* d_in, const int* in_sizes, int n_in,
                              void* d_out, int out_size)
{
    (void)in_sizes; (void)n_in; (void)out_size;
    const float* theta = (const float*)d_in[0];
    float* out = (float*)d_out;

    cudaFuncSetAttribute(viterbi_fwd,
                         cudaFuncAttributeMaxDynamicSharedMemorySize,
                         PIPE * TILE_BYTES);
    viterbi_fwd<<<NB * 4, NTHR, PIPE * TILE_BYTES>>>(theta, out);
}